// round 15
// baseline (speedup 1.0000x reference)
#include <cuda_runtime.h>
#include <cuda_bf16.h>
#include <stdint.h>

// B=1024, K=4, E=16, H=2048, I=2048 (fp32 in/out)
#define NE   16
#define HD   2048
#define ID   2048
#define I2D  4096
#define NP   4096
#define BM   128
#define BN   128
#define KT   32            // k elements per smem stage
#define NIT  64            // 2048 / 32
#define NTH  512           // 16 warps, 4x4 warp grid, 32x32 per warp
#define SROW 80            // smem row stride bytes (32 bf16 = 64B data + 16B pad)
#define MATB (128 * SROW)  // 10240 B per matrix tile
#define SA_H 0
#define SA_L (1 * MATB)
#define SB_H (2 * MATB)
#define SB_L (3 * MATB)
#define STAGEB (4 * MATB)            // 40960
#define NSTG 3
#define PS_OFF (NSTG * STAGEB)       // 122880
#define AR_OFF (PS_OFF + 512)
#define SMEM_TOTAL (AR_OFF + 512)    // 123904

__device__ int d_cnt[NE];
__device__ int d_bucket[NE][NP];
__device__ __nv_bfloat16 d_gh[(size_t)NP * ID];
__device__ __nv_bfloat16 d_gl[(size_t)NP * ID];

// ---------------- helpers ----------------
__device__ __forceinline__ uint32_t smem_u32(const void* p) {
    uint32_t a;
    asm("{ .reg .u64 t; cvta.to.shared.u64 t, %1; cvt.u32.u64 %0, t; }" : "=r"(a) : "l"(p));
    return a;
}
__device__ __forceinline__ void ldsm4(uint32_t* r, uint32_t a) {
    asm volatile("ldmatrix.sync.aligned.m8n8.x4.shared.b16 {%0,%1,%2,%3}, [%4];"
                 : "=r"(r[0]), "=r"(r[1]), "=r"(r[2]), "=r"(r[3]) : "r"(a));
}
__device__ __forceinline__ void mma16816(float* c, const uint32_t* a, uint32_t b0, uint32_t b1) {
    asm volatile("mma.sync.aligned.m16n8k16.row.col.f32.bf16.bf16.f32 "
                 "{%0,%1,%2,%3}, {%4,%5,%6,%7}, {%8,%9}, {%0,%1,%2,%3};"
                 : "+f"(c[0]), "+f"(c[1]), "+f"(c[2]), "+f"(c[3])
                 : "r"(a[0]), "r"(a[1]), "r"(a[2]), "r"(a[3]), "r"(b0), "r"(b1));
}
__device__ __forceinline__ void split4(float4 v, uint2& h, uint2& l) {
    __nv_bfloat162 h01 = __floats2bfloat162_rn(v.x, v.y);
    __nv_bfloat162 h23 = __floats2bfloat162_rn(v.z, v.w);
    float2 f01 = __bfloat1622float2(h01);
    float2 f23 = __bfloat1622float2(h23);
    __nv_bfloat162 l01 = __floats2bfloat162_rn(v.x - f01.x, v.y - f01.y);
    __nv_bfloat162 l23 = __floats2bfloat162_rn(v.z - f23.x, v.w - f23.y);
    h.x = *(uint32_t*)&h01; h.y = *(uint32_t*)&h23;
    l.x = *(uint32_t*)&l01; l.y = *(uint32_t*)&l23;
}
__device__ __forceinline__ float swiglu_pair(float xg, float xl) {
    xg = fminf(xg, 7.0f);
    xl = fminf(fmaxf(xl, -7.0f), 7.0f);
    float s = 1.0f / (1.0f + __expf(-1.702f * xg));
    return xg * s * (xl + 1.0f);
}

__global__ void zero_cnt_kernel() {
    if (threadIdx.x < NE) d_cnt[threadIdx.x] = 0;
}
__global__ void scatter_kernel(const int* __restrict__ idx) {
    int p = blockIdx.x * blockDim.x + threadIdx.x;
    if (p < NP) {
        int e = idx[p];
        int pos = atomicAdd(&d_cnt[e], 1);
        d_bucket[e][pos] = p;
    }
}

// -------- fragment loads (verified layout; warp tile now 32Mx32N) ----------
__device__ __forceinline__ void ldsm_hi(uint32_t sbase, uint32_t aoff, uint32_t boff, int kc,
                                        uint32_t Ah[2][4], uint32_t Bh[2][4]) {
#pragma unroll
    for (int mt = 0; mt < 2; ++mt)
        ldsm4(Ah[mt], sbase + SA_H + aoff + mt * 1280 + kc * 32);
#pragma unroll
    for (int n2 = 0; n2 < 2; ++n2)
        ldsm4(Bh[n2], sbase + SB_H + boff + n2 * 1280 + kc * 32);
}
__device__ __forceinline__ void ldsm_lo(uint32_t sbase, uint32_t aoff, uint32_t boff, int kc,
                                        uint32_t Al[2][4], uint32_t Bl[2][4]) {
#pragma unroll
    for (int mt = 0; mt < 2; ++mt)
        ldsm4(Al[mt], sbase + SA_L + aoff + mt * 1280 + kc * 32);
#pragma unroll
    for (int n2 = 0; n2 < 2; ++n2)
        ldsm4(Bl[n2], sbase + SB_L + boff + n2 * 1280 + kc * 32);
}
__device__ __forceinline__ void mma_term(float acc[8][4],
                                         const uint32_t A[2][4], const uint32_t B[2][4]) {
#pragma unroll
    for (int mt = 0; mt < 2; ++mt)
#pragma unroll
        for (int nt = 0; nt < 4; ++nt)
            mma16816(acc[mt * 4 + nt], A[mt],
                     B[nt >> 1][(nt & 1) * 2], B[nt >> 1][(nt & 1) * 2 + 1]);
}
__device__ __forceinline__ uint32_t a_ldsm_off(int wm, int lane) {
    return (uint32_t)(wm * 32 + (lane & 15)) * SROW + ((lane >> 4) * 16);
}
__device__ __forceinline__ uint32_t b_ldsm_off(int wn, int lane) {
    return (uint32_t)(wn * 32 + (lane & 7) + ((lane & 16) >> 1)) * SROW + ((lane & 8) * 2);
}

// ---------------- gate_up: g = swiglu(T_gather x W1^T + b1) -> d_gh/d_gl ----
__global__ __launch_bounds__(NTH, 1) void gate_kernel(
    const float* __restrict__ t, const float* __restrict__ w1,
    const float* __restrict__ b1) {
    const int e = blockIdx.z;
    const int M = d_cnt[e];
    const int m0 = blockIdx.x * BM;
    if (m0 >= M) return;
    const int n0 = blockIdx.y * BN;

    extern __shared__ char smem[];
    uint32_t su = smem_u32(smem);
    const int tid = threadIdx.x, lane = tid & 31, wid = tid >> 5;
    int* ps = (int*)(smem + PS_OFF);
    int* ar = (int*)(smem + AR_OFF);
    if (tid < BM) {
        int r = m0 + tid;
        int p = (r < M) ? d_bucket[e][r] : -1;
        ps[tid] = p;
        ar[tid] = (p >= 0) ? (p >> 2) : -1;
    }
    __syncthreads();

    // loader: 2 float4 chunks per matrix per thread (128 rows x 32 fp32 = 1024)
    uint32_t soff[2];
    const float* aP[2];
    const float* bP[2];
    bool avv[2];
    const float* wb = w1 + ((size_t)e * I2D + n0) * HD;
#pragma unroll
    for (int i = 0; i < 2; i++) {
        int c = tid + i * NTH;
        int row = c >> 3, c8 = c & 7;
        soff[i] = (uint32_t)row * SROW + c8 * 8;
        int tok = ar[row];
        avv[i] = (tok >= 0);
        aP[i] = t + (size_t)(tok < 0 ? 0 : tok) * HD + c8 * 4;
        bP[i] = wb + (size_t)row * HD + c8 * 4;
    }

    const int wm = wid >> 2, wn = wid & 3;
    const uint32_t aoff = a_ldsm_off(wm, lane);
    const uint32_t boff = b_ldsm_off(wn, lane);

    float acc[8][4];
#pragma unroll
    for (int i = 0; i < 8; i++) { acc[i][0] = acc[i][1] = acc[i][2] = acc[i][3] = 0.f; }

    const float4 fz = make_float4(0.f, 0.f, 0.f, 0.f);
    float4 va[2], vb[2];

#define GATE_LDG(k0_) do { const int _k0 = (k0_);                              \
    _Pragma("unroll") for (int i = 0; i < 2; i++) {                            \
        va[i] = avv[i] ? *(const float4*)(aP[i] + _k0) : fz;                   \
        vb[i] = *(const float4*)(bP[i] + _k0);                                 \
    } } while (0)
#define GATE_STS_A(stb_) do { char* _st = (stb_);                              \
    _Pragma("unroll") for (int i = 0; i < 2; i++) { uint2 h, l;                \
        split4(va[i], h, l);                                                   \
        *(uint2*)(_st + SA_H + soff[i]) = h;                                   \
        *(uint2*)(_st + SA_L + soff[i]) = l; } } while (0)
#define GATE_STS_B(stb_) do { char* _st = (stb_);                              \
    _Pragma("unroll") for (int i = 0; i < 2; i++) { uint2 h, l;                \
        split4(vb[i], h, l);                                                   \
        *(uint2*)(_st + SB_H + soff[i]) = h;                                   \
        *(uint2*)(_st + SB_L + soff[i]) = l; } } while (0)

    // prologue: fill stages 0,1; preload chunk 2; prefetch stage0 kc0 hi frags
    GATE_LDG(0);      GATE_STS_A(smem);          GATE_STS_B(smem);
    GATE_LDG(KT);     GATE_STS_A(smem + STAGEB); GATE_STS_B(smem + STAGEB);
    GATE_LDG(2 * KT);
    __syncthreads();
    uint32_t AhP[2][4], BhP[2][4];
    ldsm_hi(su, aoff, boff, 0, AhP, BhP);

    for (int it = 0; it < NIT; ++it) {
        __syncthreads();                      // stage it%3 visible; (it+2)%3 free
        const uint32_t sb  = su + (it % 3) * STAGEB;
        const uint32_t sbn = su + ((it + 1) % 3) * STAGEB;
        char* stw = smem + ((it + 2) % 3) * STAGEB;
        const bool doSts = (it + 2) < NIT;
        const bool doLdg = (it + 3) < NIT;
        const bool doPre = (it + 1) < NIT;
        // kc0: hi frags already in regs -> term1 issues with no LDSM wait
        uint32_t Al0[2][4], Bl0[2][4];
        ldsm_lo(sb, aoff, boff, 0, Al0, Bl0);
        mma_term(acc, AhP, BhP);
        if (doSts) GATE_STS_A(stw);
        mma_term(acc, AhP, Bl0);
        if (doSts) GATE_STS_B(stw);
        mma_term(acc, Al0, BhP);
        // kc1: dependency-first ordering (hi before lo)
        uint32_t Ah1[2][4], Bh1[2][4], Al1[2][4], Bl1[2][4];
        ldsm_hi(sb, aoff, boff, 1, Ah1, Bh1);
        ldsm_lo(sb, aoff, boff, 1, Al1, Bl1);
        mma_term(acc, Ah1, Bh1);
        if (doLdg) GATE_LDG((it + 3) * KT);
        mma_term(acc, Ah1, Bl1);
        // prefetch next iter's kc0 hi frags from stage (it+1)%3 (valid now)
        if (doPre) ldsm_hi(sbn, aoff, boff, 0, AhP, BhP);
        mma_term(acc, Al1, Bh1);
    }

    // epilogue: bias + swiglu -> bf16 hi/lo activations
    const int g = lane >> 2, q = lane & 3;
    const float* bb = b1 + (size_t)e * I2D;
#pragma unroll
    for (int nt = 0; nt < 4; ++nt) {
        int n = n0 + wn * 32 + nt * 8 + q * 2;
        float bn0 = __ldg(bb + n), bn1 = __ldg(bb + n + 1);
#pragma unroll
        for (int mt = 0; mt < 2; ++mt) {
            float* c = acc[mt * 4 + nt];
            int r0 = wm * 32 + mt * 16 + g;
            if (m0 + r0 < M) {
                int p = ps[r0];
                float gg = swiglu_pair(c[0] + bn0, c[1] + bn1);
                __nv_bfloat16 h = __float2bfloat16(gg);
                __nv_bfloat16 lo = __float2bfloat16(gg - __bfloat162float(h));
                size_t o = (size_t)p * ID + (n >> 1);
                d_gh[o] = h; d_gl[o] = lo;
            }
            int r1 = r0 + 8;
            if (m0 + r1 < M) {
                int p = ps[r1];
                float gg = swiglu_pair(c[2] + bn0, c[3] + bn1);
                __nv_bfloat16 h = __float2bfloat16(gg);
                __nv_bfloat16 lo = __float2bfloat16(gg - __bfloat162float(h));
                size_t o = (size_t)p * ID + (n >> 1);
                d_gh[o] = h; d_gl[o] = lo;
            }
        }
    }
}

// ---------------- down: out = G x W2^T + b2 ----------------
__global__ __launch_bounds__(NTH, 1) void down_kernel(
    const float* __restrict__ w2, const float* __restrict__ b2,
    float* __restrict__ out) {
    const int e = blockIdx.z;
    const int M = d_cnt[e];
    const int m0 = blockIdx.x * BM;
    if (m0 >= M) return;
    const int n0 = blockIdx.y * BN;

    extern __shared__ char smem[];
    uint32_t su = smem_u32(smem);
    const int tid = threadIdx.x, lane = tid & 31, wid = tid >> 5;
    int* ps = (int*)(smem + PS_OFF);
    if (tid < BM) {
        int r = m0 + tid;
        ps[tid] = (r < M) ? d_bucket[e][r] : -1;
    }
    __syncthreads();

    // A loader: bf16 hi/lo, 1 x 16B chunk per thread per matrix (512 total)
    uint32_t soffA;
    const uint4* ghP;
    const uint4* glP;
    bool avA;
    {
        int c = tid;
        int row = c >> 2, c4 = c & 3;
        soffA = (uint32_t)row * SROW + c4 * 16;
        int p = ps[row];
        avA = (p >= 0);
        size_t off = (size_t)(p < 0 ? 0 : p) * ID + c4 * 8;
        ghP = (const uint4*)(d_gh + off);
        glP = (const uint4*)(d_gl + off);
    }
    // B loader: fp32 w2 with in-loop split, 2 chunks per thread
    uint32_t soffB[2];
    const float* bP[2];
    const float* wb = w2 + ((size_t)e * HD + n0) * ID;
#pragma unroll
    for (int i = 0; i < 2; i++) {
        int c = tid + i * NTH;
        int row = c >> 3, c8 = c & 7;
        soffB[i] = (uint32_t)row * SROW + c8 * 8;
        bP[i] = wb + (size_t)row * ID + c8 * 4;
    }

    const int wm = wid >> 2, wn = wid & 3;
    const uint32_t aoff = a_ldsm_off(wm, lane);
    const uint32_t boff = b_ldsm_off(wn, lane);

    float acc[8][4];
#pragma unroll
    for (int i = 0; i < 8; i++) { acc[i][0] = acc[i][1] = acc[i][2] = acc[i][3] = 0.f; }

    const uint4 uz = make_uint4(0, 0, 0, 0);
    uint4 vah, val;
    float4 vb[2];

#define DOWN_LDG(k0_) do { const int _k0 = (k0_);                              \
    vah = avA ? __ldg((const uint4*)((const __nv_bfloat16*)ghP + _k0)) : uz;   \
    val = avA ? __ldg((const uint4*)((const __nv_bfloat16*)glP + _k0)) : uz;   \
    _Pragma("unroll") for (int i = 0; i < 2; i++)                              \
        vb[i] = *(const float4*)(bP[i] + _k0); } while (0)
#define DOWN_STS_A(stb_) do { char* _st = (stb_);                              \
    *(uint4*)(_st + SA_H + soffA) = vah;                                       \
    *(uint4*)(_st + SA_L + soffA) = val; } while (0)
#define DOWN_STS_B(stb_) do { char* _st = (stb_);                              \
    _Pragma("unroll") for (int i = 0; i < 2; i++) { uint2 h, l;                \
        split4(vb[i], h, l);                                                   \
        *(uint2*)(_st + SB_H + soffB[i]) = h;                                  \
        *(uint2*)(_st + SB_L + soffB[i]) = l; } } while (0)

    DOWN_LDG(0);      DOWN_STS_A(smem);          DOWN_STS_B(smem);
    DOWN_LDG(KT);     DOWN_STS_A(smem + STAGEB); DOWN_STS_B(smem + STAGEB);
    DOWN_LDG(2 * KT);
    __syncthreads();
    uint32_t AhP[2][4], BhP[2][4];
    ldsm_hi(su, aoff, boff, 0, AhP, BhP);

    for (int it = 0; it < NIT; ++it) {
        __syncthreads();
        const uint32_t sb  = su + (it % 3) * STAGEB;
        const uint32_t sbn = su + ((it + 1) % 3) * STAGEB;
        char* stw = smem + ((it + 2) % 3) * STAGEB;
        const bool doSts = (it + 2) < NIT;
        const bool doLdg = (it + 3) < NIT;
        const bool doPre = (it + 1) < NIT;
        uint32_t Al0[2][4], Bl0[2][4];
        ldsm_lo(sb, aoff, boff, 0, Al0, Bl0);
        mma_term(acc, AhP, BhP);
        if (doSts) DOWN_STS_A(stw);
        mma_term(acc, AhP, Bl0);
        if (doSts) DOWN_STS_B(stw);
        mma_term(acc, Al0, BhP);
        uint32_t Ah1[2][4], Bh1[2][4], Al1[2][4], Bl1[2][4];
        ldsm_hi(sb, aoff, boff, 1, Ah1, Bh1);
        ldsm_lo(sb, aoff, boff, 1, Al1, Bl1);
        mma_term(acc, Ah1, Bh1);
        if (doLdg) DOWN_LDG((it + 3) * KT);
        mma_term(acc, Ah1, Bl1);
        if (doPre) ldsm_hi(sbn, aoff, boff, 0, AhP, BhP);
        mma_term(acc, Al1, Bh1);
    }

    // epilogue: bias, fp32 out
    const int g = lane >> 2, q = lane & 3;
    const float* bb = b2 + (size_t)e * HD;
#pragma unroll
    for (int nt = 0; nt < 4; ++nt) {
        int n = n0 + wn * 32 + nt * 8 + q * 2;
        float bn0 = __ldg(bb + n), bn1 = __ldg(bb + n + 1);
#pragma unroll
        for (int mt = 0; mt < 2; ++mt) {
            float* c = acc[mt * 4 + nt];
            int r0 = wm * 32 + mt * 16 + g;
            if (m0 + r0 < M) {
                int p = ps[r0];
                float2 v = make_float2(c[0] + bn0, c[1] + bn1);
                *(float2*)(out + (size_t)p * HD + n) = v;
            }
            int r1 = r0 + 8;
            if (m0 + r1 < M) {
                int p = ps[r1];
                float2 v = make_float2(c[2] + bn0, c[3] + bn1);
                *(float2*)(out + (size_t)p * HD + n) = v;
            }
        }
    }
}

// ---------------- launch ----------------
extern "C" void kernel_launch(void* const* d_in, const int* in_sizes, int n_in,
                              void* d_out, int out_size) {
    const float* t   = (const float*)d_in[0];
    const int*   idx = (const int*)d_in[1];
    const float* w1  = (const float*)d_in[2];
    const float* b1  = (const float*)d_in[3];
    const float* w2  = (const float*)d_in[4];
    const float* b2  = (const float*)d_in[5];
    float* out = (float*)d_out;

    cudaFuncSetAttribute(gate_kernel, cudaFuncAttributeMaxDynamicSharedMemorySize, SMEM_TOTAL);
    cudaFuncSetAttribute(down_kernel, cudaFuncAttributeMaxDynamicSharedMemorySize, SMEM_TOTAL);

    zero_cnt_kernel<<<1, 32>>>();
    scatter_kernel<<<NP / 256, 256>>>(idx);
    gate_kernel<<<dim3(NP / BM, I2D / BN, NE), NTH, SMEM_TOTAL>>>(t, w1, b1);
    down_kernel<<<dim3(NP / BM, HD / BN, NE), NTH, SMEM_TOTAL>>>(w2, b2, out);
}

// round 16
// speedup vs baseline: 1.0053x; 1.0053x over previous
#include <cuda_runtime.h>
#include <cuda_bf16.h>
#include <stdint.h>

// B=1024, K=4, E=16, H=2048, I=2048 (fp32 in/out)
#define NE   16
#define HD   2048
#define ID   2048
#define I2D  4096
#define NP   4096
#define BM   128
#define BN   128
#define KT   32            // k elements per smem stage
#define NIT  64            // 2048 / 32
#define SROW 80            // smem row stride bytes (32 bf16 = 64B data + 16B pad)
#define MATB (128 * SROW)  // 10240 B per matrix tile
#define SA_H 0
#define SA_L (1 * MATB)
#define SB_H (2 * MATB)
#define SB_L (3 * MATB)
#define STAGEB (4 * MATB)            // 40960
#define NSTG 3
#define PS_OFF (NSTG * STAGEB)       // 122880
#define AR_OFF (PS_OFF + 512)
#define SMEM_TOTAL (AR_OFF + 512)    // 123904

__device__ int d_cnt[NE];
__device__ int d_bucket[NE][NP];
__device__ __nv_bfloat16 d_gh[(size_t)NP * ID];
__device__ __nv_bfloat16 d_gl[(size_t)NP * ID];

// ---------------- helpers ----------------
__device__ __forceinline__ uint32_t smem_u32(const void* p) {
    uint32_t a;
    asm("{ .reg .u64 t; cvta.to.shared.u64 t, %1; cvt.u32.u64 %0, t; }" : "=r"(a) : "l"(p));
    return a;
}
__device__ __forceinline__ void ldsm4(uint32_t* r, uint32_t a) {
    asm volatile("ldmatrix.sync.aligned.m8n8.x4.shared.b16 {%0,%1,%2,%3}, [%4];"
                 : "=r"(r[0]), "=r"(r[1]), "=r"(r[2]), "=r"(r[3]) : "r"(a));
}
__device__ __forceinline__ void mma16816(float* c, const uint32_t* a, uint32_t b0, uint32_t b1) {
    asm volatile("mma.sync.aligned.m16n8k16.row.col.f32.bf16.bf16.f32 "
                 "{%0,%1,%2,%3}, {%4,%5,%6,%7}, {%8,%9}, {%0,%1,%2,%3};"
                 : "+f"(c[0]), "+f"(c[1]), "+f"(c[2]), "+f"(c[3])
                 : "r"(a[0]), "r"(a[1]), "r"(a[2]), "r"(a[3]), "r"(b0), "r"(b1));
}
__device__ __forceinline__ void split4(float4 v, uint2& h, uint2& l) {
    __nv_bfloat162 h01 = __floats2bfloat162_rn(v.x, v.y);
    __nv_bfloat162 h23 = __floats2bfloat162_rn(v.z, v.w);
    float2 f01 = __bfloat1622float2(h01);
    float2 f23 = __bfloat1622float2(h23);
    __nv_bfloat162 l01 = __floats2bfloat162_rn(v.x - f01.x, v.y - f01.y);
    __nv_bfloat162 l23 = __floats2bfloat162_rn(v.z - f23.x, v.w - f23.y);
    h.x = *(uint32_t*)&h01; h.y = *(uint32_t*)&h23;
    l.x = *(uint32_t*)&l01; l.y = *(uint32_t*)&l23;
}
__device__ __forceinline__ float swiglu_pair(float xg, float xl) {
    xg = fminf(xg, 7.0f);
    xl = fminf(fmaxf(xl, -7.0f), 7.0f);
    float s = 1.0f / (1.0f + __expf(-1.702f * xg));
    return xg * s * (xl + 1.0f);
}

__global__ void zero_cnt_kernel() {
    if (threadIdx.x < NE) d_cnt[threadIdx.x] = 0;
}
__global__ void scatter_kernel(const int* __restrict__ idx) {
    int p = blockIdx.x * blockDim.x + threadIdx.x;
    if (p < NP) {
        int e = idx[p];
        int pos = atomicAdd(&d_cnt[e], 1);
        d_bucket[e][pos] = p;
    }
}

// ---------------- fragment loads (verified R8 layout), hi/lo separated ------
__device__ __forceinline__ void ldsm_hi(uint32_t sbase, uint32_t aoff, uint32_t boff, int kc,
                                        uint32_t Ah[4][4], uint32_t Bh[2][4]) {
#pragma unroll
    for (int mt = 0; mt < 4; ++mt)
        ldsm4(Ah[mt], sbase + SA_H + aoff + mt * 1280 + kc * 32);
#pragma unroll
    for (int n2 = 0; n2 < 2; ++n2)
        ldsm4(Bh[n2], sbase + SB_H + boff + n2 * 1280 + kc * 32);
}
__device__ __forceinline__ void ldsm_lo(uint32_t sbase, uint32_t aoff, uint32_t boff, int kc,
                                        uint32_t Al[4][4], uint32_t Bl[2][4]) {
#pragma unroll
    for (int mt = 0; mt < 4; ++mt)
        ldsm4(Al[mt], sbase + SA_L + aoff + mt * 1280 + kc * 32);
#pragma unroll
    for (int n2 = 0; n2 < 2; ++n2)
        ldsm4(Bl[n2], sbase + SB_L + boff + n2 * 1280 + kc * 32);
}
__device__ __forceinline__ void mma_term(float acc[16][4],
                                         const uint32_t A[4][4], const uint32_t B[2][4]) {
#pragma unroll
    for (int mt = 0; mt < 4; ++mt)
#pragma unroll
        for (int nt = 0; nt < 4; ++nt)
            mma16816(acc[mt * 4 + nt], A[mt],
                     B[nt >> 1][(nt & 1) * 2], B[nt >> 1][(nt & 1) * 2 + 1]);
}
__device__ __forceinline__ uint32_t a_ldsm_off(int wm, int lane) {
    return (uint32_t)(wm * 64 + (lane & 15)) * SROW + ((lane >> 4) * 16);
}
__device__ __forceinline__ uint32_t b_ldsm_off(int wn, int lane) {
    return (uint32_t)(wn * 32 + (lane & 7) + ((lane & 16) >> 1)) * SROW + ((lane & 8) * 2);
}

// ---------------- gate_up: g = swiglu(T_gather x W1^T + b1) -> d_gh/d_gl ----
__global__ __launch_bounds__(256, 1) void gate_kernel(
    const float* __restrict__ t, const float* __restrict__ w1,
    const float* __restrict__ b1) {
    const int e = blockIdx.z;
    const int M = d_cnt[e];
    const int m0 = blockIdx.x * BM;
    if (m0 >= M) return;
    const int n0 = blockIdx.y * BN;

    extern __shared__ char smem[];
    uint32_t su = smem_u32(smem);
    const int tid = threadIdx.x, lane = tid & 31, wid = tid >> 5;
    int* ps = (int*)(smem + PS_OFF);
    int* ar = (int*)(smem + AR_OFF);
    if (tid < BM) {
        int r = m0 + tid;
        int p = (r < M) ? d_bucket[e][r] : -1;
        ps[tid] = p;
        ar[tid] = (p >= 0) ? (p >> 2) : -1;
    }
    __syncthreads();

    uint32_t soff[4];
    const float* aP[4];
    const float* bP[4];
    bool avv[4];
    const float* wb = w1 + ((size_t)e * I2D + n0) * HD;
#pragma unroll
    for (int i = 0; i < 4; i++) {
        int c = tid + i * 256;
        int row = c >> 3, c8 = c & 7;
        soff[i] = (uint32_t)row * SROW + c8 * 8;
        int tok = ar[row];
        avv[i] = (tok >= 0);
        aP[i] = t + (size_t)(tok < 0 ? 0 : tok) * HD + c8 * 4;
        bP[i] = wb + (size_t)row * HD + c8 * 4;
    }

    const int wm = wid >> 2, wn = wid & 3;
    const uint32_t aoff = a_ldsm_off(wm, lane);
    const uint32_t boff = b_ldsm_off(wn, lane);

    float acc[16][4];
#pragma unroll
    for (int i = 0; i < 16; i++) { acc[i][0] = acc[i][1] = acc[i][2] = acc[i][3] = 0.f; }

    const float4 fz = make_float4(0.f, 0.f, 0.f, 0.f);
    float4 va[4], vb[4];

#define GATE_LDG(k0_) do { const int _k0 = (k0_);                              \
    _Pragma("unroll") for (int i = 0; i < 4; i++) {                            \
        va[i] = avv[i] ? *(const float4*)(aP[i] + _k0) : fz;                   \
        vb[i] = *(const float4*)(bP[i] + _k0);                                 \
    } } while (0)
#define GATE_STS_A(stb_) do { char* _st = (stb_);                              \
    _Pragma("unroll") for (int i = 0; i < 4; i++) { uint2 h, l;                \
        split4(va[i], h, l);                                                   \
        *(uint2*)(_st + SA_H + soff[i]) = h;                                   \
        *(uint2*)(_st + SA_L + soff[i]) = l; } } while (0)
#define GATE_STS_B(stb_) do { char* _st = (stb_);                              \
    _Pragma("unroll") for (int i = 0; i < 4; i++) { uint2 h, l;                \
        split4(vb[i], h, l);                                                   \
        *(uint2*)(_st + SB_H + soff[i]) = h;                                   \
        *(uint2*)(_st + SB_L + soff[i]) = l; } } while (0)

    // prologue: fill stages 0,1; preload chunk 2; prefetch stage0 kc0 hi frags
    GATE_LDG(0);      GATE_STS_A(smem);          GATE_STS_B(smem);
    GATE_LDG(KT);     GATE_STS_A(smem + STAGEB); GATE_STS_B(smem + STAGEB);
    GATE_LDG(2 * KT);
    __syncthreads();
    uint32_t AhP[4][4], BhP[2][4];
    ldsm_hi(su, aoff, boff, 0, AhP, BhP);

    for (int it = 0; it < NIT; ++it) {
        __syncthreads();                      // stage it%3 visible; (it+2)%3 free
        const uint32_t sb  = su + (it % 3) * STAGEB;
        const uint32_t sbn = su + ((it + 1) % 3) * STAGEB;
        char* stw = smem + ((it + 2) % 3) * STAGEB;
        const bool doSts = (it + 2) < NIT;
        const bool doLdg = (it + 3) < NIT;
        const bool doPre = (it + 1) < NIT;
        // kc0: hi frags already in regs -> term1 issues with no LDSM wait
        uint32_t Al0[4][4], Bl0[2][4];
        ldsm_lo(sb, aoff, boff, 0, Al0, Bl0);
        mma_term(acc, AhP, BhP);
        if (doSts) GATE_STS_A(stw);
        mma_term(acc, AhP, Bl0);
        // HOIST: kc1 hi frags load 2 term-groups before use (latency covered)
        uint32_t Ah1[4][4], Bh1[2][4];
        ldsm_hi(sb, aoff, boff, 1, Ah1, Bh1);
        if (doSts) GATE_STS_B(stw);
        mma_term(acc, Al0, BhP);
        // kc1 lo frags: one term-group of cover
        uint32_t Al1[4][4], Bl1[2][4];
        ldsm_lo(sb, aoff, boff, 1, Al1, Bl1);
        mma_term(acc, Ah1, Bh1);
        if (doLdg) GATE_LDG((it + 3) * KT);
        mma_term(acc, Ah1, Bl1);
        // prefetch next iter's kc0 hi frags from stage (it+1)%3 (valid now)
        if (doPre) ldsm_hi(sbn, aoff, boff, 0, AhP, BhP);
        mma_term(acc, Al1, Bh1);
    }

    // epilogue: bias + swiglu -> bf16 hi/lo activations
    const int g = lane >> 2, q = lane & 3;
    const float* bb = b1 + (size_t)e * I2D;
#pragma unroll
    for (int nt = 0; nt < 4; ++nt) {
        int n = n0 + wn * 32 + nt * 8 + q * 2;
        float bn0 = __ldg(bb + n), bn1 = __ldg(bb + n + 1);
#pragma unroll
        for (int mt = 0; mt < 4; ++mt) {
            float* c = acc[mt * 4 + nt];
            int r0 = wm * 64 + mt * 16 + g;
            if (m0 + r0 < M) {
                int p = ps[r0];
                float gg = swiglu_pair(c[0] + bn0, c[1] + bn1);
                __nv_bfloat16 h = __float2bfloat16(gg);
                __nv_bfloat16 lo = __float2bfloat16(gg - __bfloat162float(h));
                size_t o = (size_t)p * ID + (n >> 1);
                d_gh[o] = h; d_gl[o] = lo;
            }
            int r1 = r0 + 8;
            if (m0 + r1 < M) {
                int p = ps[r1];
                float gg = swiglu_pair(c[2] + bn0, c[3] + bn1);
                __nv_bfloat16 h = __float2bfloat16(gg);
                __nv_bfloat16 lo = __float2bfloat16(gg - __bfloat162float(h));
                size_t o = (size_t)p * ID + (n >> 1);
                d_gh[o] = h; d_gl[o] = lo;
            }
        }
    }
}

// ---------------- down: out = G x W2^T + b2 ----------------
__global__ __launch_bounds__(256, 1) void down_kernel(
    const float* __restrict__ w2, const float* __restrict__ b2,
    float* __restrict__ out) {
    const int e = blockIdx.z;
    const int M = d_cnt[e];
    const int m0 = blockIdx.x * BM;
    if (m0 >= M) return;
    const int n0 = blockIdx.y * BN;

    extern __shared__ char smem[];
    uint32_t su = smem_u32(smem);
    const int tid = threadIdx.x, lane = tid & 31, wid = tid >> 5;
    int* ps = (int*)(smem + PS_OFF);
    if (tid < BM) {
        int r = m0 + tid;
        ps[tid] = (r < M) ? d_bucket[e][r] : -1;
    }
    __syncthreads();

    uint32_t soffA[2];
    const uint4* ghP[2];
    const uint4* glP[2];
    bool avA[2];
#pragma unroll
    for (int i = 0; i < 2; i++) {
        int c = tid + i * 256;
        int row = c >> 2, c4 = c & 3;
        soffA[i] = (uint32_t)row * SROW + c4 * 16;
        int p = ps[row];
        avA[i] = (p >= 0);
        size_t off = (size_t)(p < 0 ? 0 : p) * ID + c4 * 8;
        ghP[i] = (const uint4*)(d_gh + off);
        glP[i] = (const uint4*)(d_gl + off);
    }
    uint32_t soffB[4];
    const float* bP[4];
    const float* wb = w2 + ((size_t)e * HD + n0) * ID;
#pragma unroll
    for (int i = 0; i < 4; i++) {
        int c = tid + i * 256;
        int row = c >> 3, c8 = c & 7;
        soffB[i] = (uint32_t)row * SROW + c8 * 8;
        bP[i] = wb + (size_t)row * ID + c8 * 4;
    }

    const int wm = wid >> 2, wn = wid & 3;
    const uint32_t aoff = a_ldsm_off(wm, lane);
    const uint32_t boff = b_ldsm_off(wn, lane);

    float acc[16][4];
#pragma unroll
    for (int i = 0; i < 16; i++) { acc[i][0] = acc[i][1] = acc[i][2] = acc[i][3] = 0.f; }

    const uint4 uz = make_uint4(0, 0, 0, 0);
    uint4 vah[2], val[2];
    float4 vb[4];

#define DOWN_LDG(k0_) do { const int _k0 = (k0_);                              \
    _Pragma("unroll") for (int i = 0; i < 2; i++) {                            \
        vah[i] = avA[i] ? __ldg((const uint4*)((const __nv_bfloat16*)ghP[i] + _k0)) : uz; \
        val[i] = avA[i] ? __ldg((const uint4*)((const __nv_bfloat16*)glP[i] + _k0)) : uz; \
    }                                                                          \
    _Pragma("unroll") for (int i = 0; i < 4; i++)                              \
        vb[i] = *(const float4*)(bP[i] + _k0); } while (0)
#define DOWN_STS_A(stb_) do { char* _st = (stb_);                              \
    _Pragma("unroll") for (int i = 0; i < 2; i++) {                            \
        *(uint4*)(_st + SA_H + soffA[i]) = vah[i];                             \
        *(uint4*)(_st + SA_L + soffA[i]) = val[i]; } } while (0)
#define DOWN_STS_B(stb_) do { char* _st = (stb_);                              \
    _Pragma("unroll") for (int i = 0; i < 4; i++) { uint2 h, l;                \
        split4(vb[i], h, l);                                                   \
        *(uint2*)(_st + SB_H + soffB[i]) = h;                                  \
        *(uint2*)(_st + SB_L + soffB[i]) = l; } } while (0)

    DOWN_LDG(0);      DOWN_STS_A(smem);          DOWN_STS_B(smem);
    DOWN_LDG(KT);     DOWN_STS_A(smem + STAGEB); DOWN_STS_B(smem + STAGEB);
    DOWN_LDG(2 * KT);
    __syncthreads();
    uint32_t AhP[4][4], BhP[2][4];
    ldsm_hi(su, aoff, boff, 0, AhP, BhP);

    for (int it = 0; it < NIT; ++it) {
        __syncthreads();
        const uint32_t sb  = su + (it % 3) * STAGEB;
        const uint32_t sbn = su + ((it + 1) % 3) * STAGEB;
        char* stw = smem + ((it + 2) % 3) * STAGEB;
        const bool doSts = (it + 2) < NIT;
        const bool doLdg = (it + 3) < NIT;
        const bool doPre = (it + 1) < NIT;
        uint32_t Al0[4][4], Bl0[2][4];
        ldsm_lo(sb, aoff, boff, 0, Al0, Bl0);
        mma_term(acc, AhP, BhP);
        if (doSts) DOWN_STS_A(stw);
        mma_term(acc, AhP, Bl0);
        // HOIST: kc1 hi frags load 2 term-groups before use
        uint32_t Ah1[4][4], Bh1[2][4];
        ldsm_hi(sb, aoff, boff, 1, Ah1, Bh1);
        if (doSts) DOWN_STS_B(stw);
        mma_term(acc, Al0, BhP);
        uint32_t Al1[4][4], Bl1[2][4];
        ldsm_lo(sb, aoff, boff, 1, Al1, Bl1);
        mma_term(acc, Ah1, Bh1);
        if (doLdg) DOWN_LDG((it + 3) * KT);
        mma_term(acc, Ah1, Bl1);
        if (doPre) ldsm_hi(sbn, aoff, boff, 0, AhP, BhP);
        mma_term(acc, Al1, Bh1);
    }

    // epilogue: bias, fp32 out
    const int g = lane >> 2, q = lane & 3;
    const float* bb = b2 + (size_t)e * HD;
#pragma unroll
    for (int nt = 0; nt < 4; ++nt) {
        int n = n0 + wn * 32 + nt * 8 + q * 2;
        float bn0 = __ldg(bb + n), bn1 = __ldg(bb + n + 1);
#pragma unroll
        for (int mt = 0; mt < 4; ++mt) {
            float* c = acc[mt * 4 + nt];
            int r0 = wm * 64 + mt * 16 + g;
            if (m0 + r0 < M) {
                int p = ps[r0];
                float2 v = make_float2(c[0] + bn0, c[1] + bn1);
                *(float2*)(out + (size_t)p * HD + n) = v;
            }
            int r1 = r0 + 8;
            if (m0 + r1 < M) {
                int p = ps[r1];
                float2 v = make_float2(c[2] + bn0, c[3] + bn1);
                *(float2*)(out + (size_t)p * HD + n) = v;
            }
        }
    }
}

// ---------------- launch ----------------
extern "C" void kernel_launch(void* const* d_in, const int* in_sizes, int n_in,
                              void* d_out, int out_size) {
    const float* t   = (const float*)d_in[0];
    const int*   idx = (const int*)d_in[1];
    const float* w1  = (const float*)d_in[2];
    const float* b1  = (const float*)d_in[3];
    const float* w2  = (const float*)d_in[4];
    const float* b2  = (const float*)d_in[5];
    float* out = (float*)d_out;

    cudaFuncSetAttribute(gate_kernel, cudaFuncAttributeMaxDynamicSharedMemorySize, SMEM_TOTAL);
    cudaFuncSetAttribute(down_kernel, cudaFuncAttributeMaxDynamicSharedMemorySize, SMEM_TOTAL);

    zero_cnt_kernel<<<1, 32>>>();
    scatter_kernel<<<NP / 256, 256>>>(idx);
    gate_kernel<<<dim3(NP / BM, I2D / BN, NE), 256, SMEM_TOTAL>>>(t, w1, b1);
    down_kernel<<<dim3(NP / BM, HD / BN, NE), 256, SMEM_TOTAL>>>(w2, b2, out);
}

// round 17
// speedup vs baseline: 1.0085x; 1.0031x over previous
#include <cuda_runtime.h>
#include <cuda_bf16.h>
#include <stdint.h>

// B=1024, K=4, E=16, H=2048, I=2048 (fp32 in/out)
#define NE   16
#define HD   2048
#define ID   2048
#define I2D  4096
#define NP   4096
#define BM   128
#define BN   128
#define KT   32            // k elements per smem stage
#define NIT  64            // 2048 / 32
#define SROW 80            // smem row stride bytes (32 bf16 = 64B data + 16B pad)
#define MATB (128 * SROW)  // 10240 B per matrix tile
#define SA_H 0
#define SA_L (1 * MATB)
#define SB_H (2 * MATB)
#define SB_L (3 * MATB)
#define STAGEB (4 * MATB)            // 40960
#define NSTG 3
#define PS_OFF (NSTG * STAGEB)       // 122880
#define AR_OFF (PS_OFF + 512)
#define SMEM_TOTAL (AR_OFF + 512)    // 123904

__device__ int d_cnt[NE];
__device__ int d_bucket[NE][NP];
__device__ __nv_bfloat16 d_gh[(size_t)NP * ID];
__device__ __nv_bfloat16 d_gl[(size_t)NP * ID];

// ---------------- helpers ----------------
__device__ __forceinline__ uint32_t smem_u32(const void* p) {
    uint32_t a;
    asm("{ .reg .u64 t; cvta.to.shared.u64 t, %1; cvt.u32.u64 %0, t; }" : "=r"(a) : "l"(p));
    return a;
}
__device__ __forceinline__ void ldsm4(uint32_t* r, uint32_t a) {
    asm volatile("ldmatrix.sync.aligned.m8n8.x4.shared.b16 {%0,%1,%2,%3}, [%4];"
                 : "=r"(r[0]), "=r"(r[1]), "=r"(r[2]), "=r"(r[3]) : "r"(a));
}
__device__ __forceinline__ void mma16816(float* c, const uint32_t* a, uint32_t b0, uint32_t b1) {
    asm volatile("mma.sync.aligned.m16n8k16.row.col.f32.bf16.bf16.f32 "
                 "{%0,%1,%2,%3}, {%4,%5,%6,%7}, {%8,%9}, {%0,%1,%2,%3};"
                 : "+f"(c[0]), "+f"(c[1]), "+f"(c[2]), "+f"(c[3])
                 : "r"(a[0]), "r"(a[1]), "r"(a[2]), "r"(a[3]), "r"(b0), "r"(b1));
}
// two adjacent float4 (8 fp32 of one row) -> 16B hi + 16B lo
__device__ __forceinline__ void split8(float4 v0, float4 v1, uint4& h, uint4& l) {
    __nv_bfloat162 h01 = __floats2bfloat162_rn(v0.x, v0.y);
    __nv_bfloat162 h23 = __floats2bfloat162_rn(v0.z, v0.w);
    __nv_bfloat162 h45 = __floats2bfloat162_rn(v1.x, v1.y);
    __nv_bfloat162 h67 = __floats2bfloat162_rn(v1.z, v1.w);
    float2 f01 = __bfloat1622float2(h01);
    float2 f23 = __bfloat1622float2(h23);
    float2 f45 = __bfloat1622float2(h45);
    float2 f67 = __bfloat1622float2(h67);
    __nv_bfloat162 l01 = __floats2bfloat162_rn(v0.x - f01.x, v0.y - f01.y);
    __nv_bfloat162 l23 = __floats2bfloat162_rn(v0.z - f23.x, v0.w - f23.y);
    __nv_bfloat162 l45 = __floats2bfloat162_rn(v1.x - f45.x, v1.y - f45.y);
    __nv_bfloat162 l67 = __floats2bfloat162_rn(v1.z - f67.x, v1.w - f67.y);
    h.x = *(uint32_t*)&h01; h.y = *(uint32_t*)&h23;
    h.z = *(uint32_t*)&h45; h.w = *(uint32_t*)&h67;
    l.x = *(uint32_t*)&l01; l.y = *(uint32_t*)&l23;
    l.z = *(uint32_t*)&l45; l.w = *(uint32_t*)&l67;
}
__device__ __forceinline__ float swiglu_pair(float xg, float xl) {
    xg = fminf(xg, 7.0f);
    xl = fminf(fmaxf(xl, -7.0f), 7.0f);
    float s = 1.0f / (1.0f + __expf(-1.702f * xg));
    return xg * s * (xl + 1.0f);
}

__global__ void zero_cnt_kernel() {
    if (threadIdx.x < NE) d_cnt[threadIdx.x] = 0;
}
__global__ void scatter_kernel(const int* __restrict__ idx) {
    int p = blockIdx.x * blockDim.x + threadIdx.x;
    if (p < NP) {
        int e = idx[p];
        int pos = atomicAdd(&d_cnt[e], 1);
        d_bucket[e][pos] = p;
    }
}

// ---------------- fragment loads (verified R8 layout), hi/lo separated ------
__device__ __forceinline__ void ldsm_hi(uint32_t sbase, uint32_t aoff, uint32_t boff, int kc,
                                        uint32_t Ah[4][4], uint32_t Bh[2][4]) {
#pragma unroll
    for (int mt = 0; mt < 4; ++mt)
        ldsm4(Ah[mt], sbase + SA_H + aoff + mt * 1280 + kc * 32);
#pragma unroll
    for (int n2 = 0; n2 < 2; ++n2)
        ldsm4(Bh[n2], sbase + SB_H + boff + n2 * 1280 + kc * 32);
}
__device__ __forceinline__ void ldsm_lo(uint32_t sbase, uint32_t aoff, uint32_t boff, int kc,
                                        uint32_t Al[4][4], uint32_t Bl[2][4]) {
#pragma unroll
    for (int mt = 0; mt < 4; ++mt)
        ldsm4(Al[mt], sbase + SA_L + aoff + mt * 1280 + kc * 32);
#pragma unroll
    for (int n2 = 0; n2 < 2; ++n2)
        ldsm4(Bl[n2], sbase + SB_L + boff + n2 * 1280 + kc * 32);
}
__device__ __forceinline__ void mma_term(float acc[16][4],
                                         const uint32_t A[4][4], const uint32_t B[2][4]) {
#pragma unroll
    for (int mt = 0; mt < 4; ++mt)
#pragma unroll
        for (int nt = 0; nt < 4; ++nt)
            mma16816(acc[mt * 4 + nt], A[mt],
                     B[nt >> 1][(nt & 1) * 2], B[nt >> 1][(nt & 1) * 2 + 1]);
}
__device__ __forceinline__ uint32_t a_ldsm_off(int wm, int lane) {
    return (uint32_t)(wm * 64 + (lane & 15)) * SROW + ((lane >> 4) * 16);
}
__device__ __forceinline__ uint32_t b_ldsm_off(int wn, int lane) {
    return (uint32_t)(wn * 32 + (lane & 7) + ((lane & 16) >> 1)) * SROW + ((lane & 8) * 2);
}

// ---------------- gate_up: g = swiglu(T_gather x W1^T + b1) -> d_gh/d_gl ----
__global__ __launch_bounds__(256, 1) void gate_kernel(
    const float* __restrict__ t, const float* __restrict__ w1,
    const float* __restrict__ b1) {
    const int e = blockIdx.z;
    const int M = d_cnt[e];
    const int m0 = blockIdx.x * BM;
    if (m0 >= M) return;
    const int n0 = blockIdx.y * BN;

    extern __shared__ char smem[];
    uint32_t su = smem_u32(smem);
    const int tid = threadIdx.x, lane = tid & 31, wid = tid >> 5;
    int* ps = (int*)(smem + PS_OFF);
    int* ar = (int*)(smem + AR_OFF);
    if (tid < BM) {
        int r = m0 + tid;
        int p = (r < M) ? d_bucket[e][r] : -1;
        ps[tid] = p;
        ar[tid] = (p >= 0) ? (p >> 2) : -1;
    }
    __syncthreads();

    // loader: 2 units/thread, each unit = 8 consecutive fp32 of one row
    // unit u: row = u>>2, uc = u&3 (32B fp32 -> 16B bf16 at row*SROW + uc*16)
    uint32_t soff[2];
    const float* aP[2];
    const float* bP[2];
    bool avv[2];
    const float* wb = w1 + ((size_t)e * I2D + n0) * HD;
#pragma unroll
    for (int i = 0; i < 2; i++) {
        int u = tid + i * 256;
        int row = u >> 2, uc = u & 3;
        soff[i] = (uint32_t)row * SROW + uc * 16;
        int tok = ar[row];
        avv[i] = (tok >= 0);
        aP[i] = t + (size_t)(tok < 0 ? 0 : tok) * HD + uc * 8;
        bP[i] = wb + (size_t)row * HD + uc * 8;
    }

    const int wm = wid >> 2, wn = wid & 3;
    const uint32_t aoff = a_ldsm_off(wm, lane);
    const uint32_t boff = b_ldsm_off(wn, lane);

    float acc[16][4];
#pragma unroll
    for (int i = 0; i < 16; i++) { acc[i][0] = acc[i][1] = acc[i][2] = acc[i][3] = 0.f; }

    const float4 fz = make_float4(0.f, 0.f, 0.f, 0.f);
    float4 va[4], vb[4];   // [2i], [2i+1] = the two float4 of unit i

#define GATE_LDG(k0_) do { const int _k0 = (k0_);                              \
    _Pragma("unroll") for (int i = 0; i < 2; i++) {                            \
        va[2*i]   = avv[i] ? *(const float4*)(aP[i] + _k0)     : fz;           \
        va[2*i+1] = avv[i] ? *(const float4*)(aP[i] + _k0 + 4) : fz;           \
        vb[2*i]   = *(const float4*)(bP[i] + _k0);                             \
        vb[2*i+1] = *(const float4*)(bP[i] + _k0 + 4);                         \
    } } while (0)
#define GATE_STS_A(stb_) do { char* _st = (stb_);                              \
    _Pragma("unroll") for (int i = 0; i < 2; i++) { uint4 h, l;                \
        split8(va[2*i], va[2*i+1], h, l);                                      \
        *(uint4*)(_st + SA_H + soff[i]) = h;                                   \
        *(uint4*)(_st + SA_L + soff[i]) = l; } } while (0)
#define GATE_STS_B(stb_) do { char* _st = (stb_);                              \
    _Pragma("unroll") for (int i = 0; i < 2; i++) { uint4 h, l;                \
        split8(vb[2*i], vb[2*i+1], h, l);                                      \
        *(uint4*)(_st + SB_H + soff[i]) = h;                                   \
        *(uint4*)(_st + SB_L + soff[i]) = l; } } while (0)

    // prologue: fill stages 0,1; preload chunk 2; prefetch stage0 kc0 hi frags
    GATE_LDG(0);      GATE_STS_A(smem);          GATE_STS_B(smem);
    GATE_LDG(KT);     GATE_STS_A(smem + STAGEB); GATE_STS_B(smem + STAGEB);
    GATE_LDG(2 * KT);
    __syncthreads();
    uint32_t AhP[4][4], BhP[2][4];
    ldsm_hi(su, aoff, boff, 0, AhP, BhP);

    for (int it = 0; it < NIT; ++it) {
        __syncthreads();                      // stage it%3 visible; (it+2)%3 free
        const uint32_t sb  = su + (it % 3) * STAGEB;
        const uint32_t sbn = su + ((it + 1) % 3) * STAGEB;
        char* stw = smem + ((it + 2) % 3) * STAGEB;
        const bool doSts = (it + 2) < NIT;
        const bool doLdg = (it + 3) < NIT;
        const bool doPre = (it + 1) < NIT;
        // kc0: hi frags already in regs -> term1 issues with no LDSM wait
        uint32_t Al0[4][4], Bl0[2][4];
        ldsm_lo(sb, aoff, boff, 0, Al0, Bl0);
        mma_term(acc, AhP, BhP);
        if (doSts) GATE_STS_A(stw);
        mma_term(acc, AhP, Bl0);
        if (doSts) GATE_STS_B(stw);
        mma_term(acc, Al0, BhP);
        // kc1: dependency-first ordering (hi before lo)
        uint32_t Ah1[4][4], Bh1[2][4], Al1[4][4], Bl1[2][4];
        ldsm_hi(sb, aoff, boff, 1, Ah1, Bh1);
        ldsm_lo(sb, aoff, boff, 1, Al1, Bl1);
        mma_term(acc, Ah1, Bh1);
        if (doLdg) GATE_LDG((it + 3) * KT);
        mma_term(acc, Ah1, Bl1);
        // prefetch next iter's kc0 hi frags from stage (it+1)%3 (valid now)
        if (doPre) ldsm_hi(sbn, aoff, boff, 0, AhP, BhP);
        mma_term(acc, Al1, Bh1);
    }

    // epilogue: bias + swiglu -> bf16 hi/lo activations
    const int g = lane >> 2, q = lane & 3;
    const float* bb = b1 + (size_t)e * I2D;
#pragma unroll
    for (int nt = 0; nt < 4; ++nt) {
        int n = n0 + wn * 32 + nt * 8 + q * 2;
        float bn0 = __ldg(bb + n), bn1 = __ldg(bb + n + 1);
#pragma unroll
        for (int mt = 0; mt < 4; ++mt) {
            float* c = acc[mt * 4 + nt];
            int r0 = wm * 64 + mt * 16 + g;
            if (m0 + r0 < M) {
                int p = ps[r0];
                float gg = swiglu_pair(c[0] + bn0, c[1] + bn1);
                __nv_bfloat16 h = __float2bfloat16(gg);
                __nv_bfloat16 lo = __float2bfloat16(gg - __bfloat162float(h));
                size_t o = (size_t)p * ID + (n >> 1);
                d_gh[o] = h; d_gl[o] = lo;
            }
            int r1 = r0 + 8;
            if (m0 + r1 < M) {
                int p = ps[r1];
                float gg = swiglu_pair(c[2] + bn0, c[3] + bn1);
                __nv_bfloat16 h = __float2bfloat16(gg);
                __nv_bfloat16 lo = __float2bfloat16(gg - __bfloat162float(h));
                size_t o = (size_t)p * ID + (n >> 1);
                d_gh[o] = h; d_gl[o] = lo;
            }
        }
    }
}

// ---------------- down: out = G x W2^T + b2 ----------------
__global__ __launch_bounds__(256, 1) void down_kernel(
    const float* __restrict__ w2, const float* __restrict__ b2,
    float* __restrict__ out) {
    const int e = blockIdx.z;
    const int M = d_cnt[e];
    const int m0 = blockIdx.x * BM;
    if (m0 >= M) return;
    const int n0 = blockIdx.y * BN;

    extern __shared__ char smem[];
    uint32_t su = smem_u32(smem);
    const int tid = threadIdx.x, lane = tid & 31, wid = tid >> 5;
    int* ps = (int*)(smem + PS_OFF);
    if (tid < BM) {
        int r = m0 + tid;
        ps[tid] = (r < M) ? d_bucket[e][r] : -1;
    }
    __syncthreads();

    // A loader: bf16 hi/lo, 2 x 16B chunks per thread per matrix (unchanged)
    uint32_t soffA[2];
    const uint4* ghP[2];
    const uint4* glP[2];
    bool avA[2];
#pragma unroll
    for (int i = 0; i < 2; i++) {
        int c = tid + i * 256;
        int row = c >> 2, c4 = c & 3;
        soffA[i] = (uint32_t)row * SROW + c4 * 16;
        int p = ps[row];
        avA[i] = (p >= 0);
        size_t off = (size_t)(p < 0 ? 0 : p) * ID + c4 * 8;
        ghP[i] = (const uint4*)(d_gh + off);
        glP[i] = (const uint4*)(d_gl + off);
    }
    // B loader: fp32 w2, 2 units/thread, 8 fp32 per unit -> 16B STS
    uint32_t soffB[2];
    const float* bP[2];
    const float* wb = w2 + ((size_t)e * HD + n0) * ID;
#pragma unroll
    for (int i = 0; i < 2; i++) {
        int u = tid + i * 256;
        int row = u >> 2, uc = u & 3;
        soffB[i] = (uint32_t)row * SROW + uc * 16;
        bP[i] = wb + (size_t)row * ID + uc * 8;
    }

    const int wm = wid >> 2, wn = wid & 3;
    const uint32_t aoff = a_ldsm_off(wm, lane);
    const uint32_t boff = b_ldsm_off(wn, lane);

    float acc[16][4];
#pragma unroll
    for (int i = 0; i < 16; i++) { acc[i][0] = acc[i][1] = acc[i][2] = acc[i][3] = 0.f; }

    const uint4 uz = make_uint4(0, 0, 0, 0);
    uint4 vah[2], val[2];
    float4 vb[4];

#define DOWN_LDG(k0_) do { const int _k0 = (k0_);                              \
    _Pragma("unroll") for (int i = 0; i < 2; i++) {                            \
        vah[i] = avA[i] ? __ldg((const uint4*)((const __nv_bfloat16*)ghP[i] + _k0)) : uz; \
        val[i] = avA[i] ? __ldg((const uint4*)((const __nv_bfloat16*)glP[i] + _k0)) : uz; \
    }                                                                          \
    _Pragma("unroll") for (int i = 0; i < 2; i++) {                            \
        vb[2*i]   = *(const float4*)(bP[i] + _k0);                             \
        vb[2*i+1] = *(const float4*)(bP[i] + _k0 + 4);                         \
    } } while (0)
#define DOWN_STS_A(stb_) do { char* _st = (stb_);                              \
    _Pragma("unroll") for (int i = 0; i < 2; i++) {                            \
        *(uint4*)(_st + SA_H + soffA[i]) = vah[i];                             \
        *(uint4*)(_st + SA_L + soffA[i]) = val[i]; } } while (0)
#define DOWN_STS_B(stb_) do { char* _st = (stb_);                              \
    _Pragma("unroll") for (int i = 0; i < 2; i++) { uint4 h, l;                \
        split8(vb[2*i], vb[2*i+1], h, l);                                      \
        *(uint4*)(_st + SB_H + soffB[i]) = h;                                  \
        *(uint4*)(_st + SB_L + soffB[i]) = l; } } while (0)

    DOWN_LDG(0);      DOWN_STS_A(smem);          DOWN_STS_B(smem);
    DOWN_LDG(KT);     DOWN_STS_A(smem + STAGEB); DOWN_STS_B(smem + STAGEB);
    DOWN_LDG(2 * KT);
    __syncthreads();
    uint32_t AhP[4][4], BhP[2][4];
    ldsm_hi(su, aoff, boff, 0, AhP, BhP);

    for (int it = 0; it < NIT; ++it) {
        __syncthreads();
        const uint32_t sb  = su + (it % 3) * STAGEB;
        const uint32_t sbn = su + ((it + 1) % 3) * STAGEB;
        char* stw = smem + ((it + 2) % 3) * STAGEB;
        const bool doSts = (it + 2) < NIT;
        const bool doLdg = (it + 3) < NIT;
        const bool doPre = (it + 1) < NIT;
        uint32_t Al0[4][4], Bl0[2][4];
        ldsm_lo(sb, aoff, boff, 0, Al0, Bl0);
        mma_term(acc, AhP, BhP);
        if (doSts) DOWN_STS_A(stw);
        mma_term(acc, AhP, Bl0);
        if (doSts) DOWN_STS_B(stw);
        mma_term(acc, Al0, BhP);
        uint32_t Ah1[4][4], Bh1[2][4], Al1[4][4], Bl1[2][4];
        ldsm_hi(sb, aoff, boff, 1, Ah1, Bh1);
        ldsm_lo(sb, aoff, boff, 1, Al1, Bl1);
        mma_term(acc, Ah1, Bh1);
        if (doLdg) DOWN_LDG((it + 3) * KT);
        mma_term(acc, Ah1, Bl1);
        if (doPre) ldsm_hi(sbn, aoff, boff, 0, AhP, BhP);
        mma_term(acc, Al1, Bh1);
    }

    // epilogue: bias, fp32 out
    const int g = lane >> 2, q = lane & 3;
    const float* bb = b2 + (size_t)e * HD;
#pragma unroll
    for (int nt = 0; nt < 4; ++nt) {
        int n = n0 + wn * 32 + nt * 8 + q * 2;
        float bn0 = __ldg(bb + n), bn1 = __ldg(bb + n + 1);
#pragma unroll
        for (int mt = 0; mt < 4; ++mt) {
            float* c = acc[mt * 4 + nt];
            int r0 = wm * 64 + mt * 16 + g;
            if (m0 + r0 < M) {
                int p = ps[r0];
                float2 v = make_float2(c[0] + bn0, c[1] + bn1);
                *(float2*)(out + (size_t)p * HD + n) = v;
            }
            int r1 = r0 + 8;
            if (m0 + r1 < M) {
                int p = ps[r1];
                float2 v = make_float2(c[2] + bn0, c[3] + bn1);
                *(float2*)(out + (size_t)p * HD + n) = v;
            }
        }
    }
}

// ---------------- launch ----------------
extern "C" void kernel_launch(void* const* d_in, const int* in_sizes, int n_in,
                              void* d_out, int out_size) {
    const float* t   = (const float*)d_in[0];
    const int*   idx = (const int*)d_in[1];
    const float* w1  = (const float*)d_in[2];
    const float* b1  = (const float*)d_in[3];
    const float* w2  = (const float*)d_in[4];
    const float* b2  = (const float*)d_in[5];
    float* out = (float*)d_out;

    cudaFuncSetAttribute(gate_kernel, cudaFuncAttributeMaxDynamicSharedMemorySize, SMEM_TOTAL);
    cudaFuncSetAttribute(down_kernel, cudaFuncAttributeMaxDynamicSharedMemorySize, SMEM_TOTAL);

    zero_cnt_kernel<<<1, 32>>>();
    scatter_kernel<<<NP / 256, 256>>>(idx);
    gate_kernel<<<dim3(NP / BM, I2D / BN, NE), 256, SMEM_TOTAL>>>(t, w1, b1);
    down_kernel<<<dim3(NP / BM, HD / BN, NE), 256, SMEM_TOTAL>>>(w2, b2, out);
}